// round 17
// baseline (speedup 1.0000x reference)
#include <cuda_runtime.h>
#include <cuda_bf16.h>
#include <math.h>
#include <stdint.h>

// Problem shapes (fixed for this dataset entry)
#define B_   128
#define N_   8
#define LQ_  32
#define LD_  256
#define D_   128
#define KT_  64           // k-rows per smem tile (4 tiles of 64 = LD), double-buffered
#define NTILES (LD_ / KT_)
#define DSTRIDE 132       // padded row stride (floats): conflict-free per 8-lane phase
#define NEGV (-9999.0f)
#define EPSV (1e-12f)

#define NT_  128          // threads per block (4 warps)

// scores[tensor][b][n]  (tensor 0 = student/cq, 1 = teacher/orig)
__device__ float g_scores[2 * B_ * N_];
// pre-normalized q: [B][LQ][D]  (2 MB, written by qnorm_kernel)
__device__ float g_qnorm[B_ * LQ_ * D_];

// Shared memory (floats): 2 d-tile buffers + per-warp partials
#define TILE_FLOATS (KT_ * DSTRIDE)
#define SMEM_FLOATS (2 * TILE_FLOATS + 8)
#define SMEM_BYTES  (SMEM_FLOATS * 4)

// Packed dual-fp32 FMA (sm_100+): acc.lo += a.lo*b.lo; acc.hi += a.hi*b.hi
#define FMA_F32X2(acc, a, b) \
    asm("fma.rn.f32x2 %0, %1, %2, %3;" : "=l"(acc) : "l"(a), "l"(b), "l"(acc))

__device__ __forceinline__ float f32x2_hsum(unsigned long long p) {
    unsigned int lo, hi;
    asm("mov.b64 {%0, %1}, %2;" : "=r"(lo), "=r"(hi) : "l"(p));
    return __uint_as_float(lo) + __uint_as_float(hi);
}

__device__ __forceinline__ void cp_async16(uint32_t saddr, const void* gptr) {
    asm volatile("cp.async.cg.shared.global [%0], [%1], 16;"
                 :: "r"(saddr), "l"(gptr));
}
#define CP_COMMIT() asm volatile("cp.async.commit_group;")

// ---- pre-kernel: L2-normalize q rows into g_qnorm ----
__global__ __launch_bounds__(NT_)
void qnorm_kernel(const float* __restrict__ q_reps)
{
    const int b  = blockIdx.x;
    const int tx = threadIdx.x & 31;
    const int ty = threadIdx.x >> 5;          // warp 0..3, rows ty*8..ty*8+7

    const float4* src = (const float4*)(q_reps + (size_t)b * LQ_ * D_);
    float4*       dst = (float4*)(g_qnorm + (size_t)b * LQ_ * D_);

    #pragma unroll
    for (int r = ty * 8; r < ty * 8 + 8; ++r) {
        float4 v = src[r * (D_ / 4) + tx];
        float ss = v.x * v.x + v.y * v.y + v.z * v.z + v.w * v.w;
        #pragma unroll
        for (int o = 16; o; o >>= 1) ss += __shfl_xor_sync(0xffffffffu, ss, o);
        float inv = 1.0f / fmaxf(sqrtf(ss), EPSV);
        v.x *= inv; v.y *= inv; v.z *= inv; v.w *= inv;
        dst[r * (D_ / 4) + tx] = v;
    }
}

__global__ __launch_bounds__(NT_, 3)
void maxsim_kernel(const float* __restrict__ d_cq,
                   const float* __restrict__ d_orig,
                   const int*   __restrict__ d_mask)
{
    extern __shared__ float sm[];
    float* d_s  = sm;                         // [2][KT_][DSTRIDE]
    float* wsum = d_s + 2 * TILE_FLOATS;      // [4]

    const int bid    = blockIdx.x;
    const int tensor = bid >> 10;             // / (N_*B_) = /1024
    const int rem    = bid & 1023;
    const int b      = rem >> 3;              // / N_
    const int n      = rem & 7;               // % N_

    const float* dptr = (tensor ? d_orig : d_cq)
                        + ((size_t)(n * B_ + b)) * (size_t)(LD_ * D_);
    const int*   mptr = d_mask + (n * B_ + b) * LD_;

    const int t  = threadIdx.x;
    const int tx = t & 31;                    // lane
    const int ty = t >> 5;                    // warp id (0..3) == q-group

    // this warp's 8 normalized q rows (global, warp-uniform reads -> L1)
    const float* qb = g_qnorm + ((size_t)b * LQ_ + ty * 8) * D_;

    // all masks for this thread's k-cols, hoisted (tile kt, col tx+32j)
    int mreg[NTILES][2];
    #pragma unroll
    for (int kt = 0; kt < NTILES; ++kt) {
        mreg[kt][0] = __ldg(mptr + kt * KT_ + tx);
        mreg[kt][1] = __ldg(mptr + kt * KT_ + tx + 32);
    }

    uint32_t sbase = (uint32_t)__cvta_generic_to_shared(d_s);

    // prefetch tile 0 into buffer 0
    {
        const float4* dg = (const float4*)dptr;
        #pragma unroll
        for (int i = t; i < KT_ * (D_ / 4); i += NT_) {
            int k = i >> 5, c = i & 31;
            cp_async16(sbase + (k * DSTRIDE + 4 * c) * 4, dg + i);
        }
        CP_COMMIT();
    }

    // running max over ALL of Ld for this thread's 8 q-rows
    float maxv[8];
    #pragma unroll
    for (int qi = 0; qi < 8; ++qi) maxv[qi] = NEGV;

    #pragma unroll
    for (int kt = 0; kt < NTILES; ++kt) {
        // prefetch next tile into the other buffer
        if (kt + 1 < NTILES) {
            const float4* dg = (const float4*)(dptr + (size_t)(kt + 1) * KT_ * D_);
            uint32_t sb = sbase + ((kt + 1) & 1) * TILE_FLOATS * 4;
            #pragma unroll
            for (int i = t; i < KT_ * (D_ / 4); i += NT_) {
                int k = i >> 5, c = i & 31;
                cp_async16(sb + (k * DSTRIDE + 4 * c) * 4, dg + i);
            }
            CP_COMMIT();
            asm volatile("cp.async.wait_group 1;");  // tile kt ready
        } else {
            asm volatile("cp.async.wait_group 0;");
        }
        __syncthreads();

        const float* buf = d_s + (kt & 1) * TILE_FLOATS;

        // register-blocked GEMM: 8 q-rows x 2 k-cols per thread.
        // d-row sq-sums (for the L2 norm) fused on the same dv registers.
        unsigned long long acc2[8][2];
        unsigned long long sq2[2];
        #pragma unroll
        for (int qi = 0; qi < 8; ++qi) { acc2[qi][0] = 0ULL; acc2[qi][1] = 0ULL; }
        sq2[0] = 0ULL; sq2[1] = 0ULL;

        const float* drow0 = buf + tx * DSTRIDE;
        const float* drow1 = buf + (tx + 32) * DSTRIDE;

        #pragma unroll 4
        for (int dd = 0; dd < D_; dd += 4) {
            ulonglong2 dv0 = *(const ulonglong2*)(drow0 + dd);
            ulonglong2 dv1 = *(const ulonglong2*)(drow1 + dd);
            FMA_F32X2(sq2[0], dv0.x, dv0.x);
            FMA_F32X2(sq2[0], dv0.y, dv0.y);
            FMA_F32X2(sq2[1], dv1.x, dv1.x);
            FMA_F32X2(sq2[1], dv1.y, dv1.y);
            #pragma unroll
            for (int qi = 0; qi < 8; ++qi) {
                ulonglong2 qv = *(const ulonglong2*)(qb + qi * D_ + dd);
                FMA_F32X2(acc2[qi][0], qv.x, dv0.x);
                FMA_F32X2(acc2[qi][0], qv.y, dv0.y);
                FMA_F32X2(acc2[qi][1], qv.x, dv1.x);
                FMA_F32X2(acc2[qi][1], qv.y, dv1.y);
            }
        }

        // epilogue: norm from fused sq-sums, mask, running max
        #pragma unroll
        for (int j = 0; j < 2; ++j) {
            if (mreg[kt][j]) {
                float nr  = fmaxf(sqrtf(f32x2_hsum(sq2[j])), EPSV);
                float inv = 1.0f / nr;
                #pragma unroll
                for (int qi = 0; qi < 8; ++qi)
                    maxv[qi] = fmaxf(maxv[qi],
                                     f32x2_hsum(acc2[qi][j]) * inv);
            }
        }
        __syncthreads();   // all warps done with buf before it is re-prefetched
    }

    // ---- lane-max completes each q-row's max over all 256 k-cols ----
    #pragma unroll
    for (int qi = 0; qi < 8; ++qi)
        #pragma unroll
        for (int o = 16; o; o >>= 1)
            maxv[qi] = fmaxf(maxv[qi], __shfl_xor_sync(0xffffffffu, maxv[qi], o));

    if (tx == 0) {
        float s = 0.f;
        #pragma unroll
        for (int qi = 0; qi < 8; ++qi) s += maxv[qi];
        wsum[ty] = s;
    }
    __syncthreads();
    if (t == 0) {
        g_scores[tensor * (B_ * N_) + b * N_ + n]
            = wsum[0] + wsum[1] + wsum[2] + wsum[3];
    }
}

__global__ void loss_kernel(float* __restrict__ out)
{
    __shared__ float part[B_];
    const int b = threadIdx.x;   // 128 threads, one per batch row

    const float* ss = g_scores + b * N_;            // student
    const float* ts = g_scores + B_ * N_ + b * N_;  // teacher

    float sv[N_], tv[N_];
    float ms = -INFINITY, mt = -INFINITY;
    #pragma unroll
    for (int j = 0; j < N_; ++j) {
        sv[j] = ss[j]; tv[j] = ts[j];
        ms = fmaxf(ms, sv[j]); mt = fmaxf(mt, tv[j]);
    }
    float es = 0.f, et = 0.f;
    #pragma unroll
    for (int j = 0; j < N_; ++j) {
        es += expf(sv[j] - ms);
        et += expf(tv[j] - mt);
    }
    float lse_s = ms + logf(es);
    float lse_t = mt + logf(et);

    float lb = 0.f;
    #pragma unroll
    for (int j = 0; j < N_; ++j) {
        float lt = tv[j] - lse_t;
        float ls = sv[j] - lse_s;
        lb += expf(lt) * (lt - ls);
    }
    part[b] = lb;
    __syncthreads();

    for (int s = 64; s > 0; s >>= 1) {
        if (b < s) part[b] += part[b + s];
        __syncthreads();
    }
    if (b == 0) out[0] = part[0] / (float)B_;
}

extern "C" void kernel_launch(void* const* d_in, const int* in_sizes, int n_in,
                              void* d_out, int out_size)
{
    const float* q_reps = (const float*)d_in[0];
    const float* d_cq   = (const float*)d_in[1];
    const float* d_orig = (const float*)d_in[2];
    const int*   d_mask = (const int*)d_in[3];
    // d_in[4] = labels (unused by the reference computation)

    cudaFuncSetAttribute(maxsim_kernel,
                         cudaFuncAttributeMaxDynamicSharedMemorySize, SMEM_BYTES);

    qnorm_kernel<<<B_, NT_>>>(q_reps);
    maxsim_kernel<<<2 * N_ * B_, NT_, SMEM_BYTES>>>(d_cq, d_orig, d_mask);
    loss_kernel<<<1, B_>>>((float*)d_out);
}